// round 10
// baseline (speedup 1.0000x reference)
#include <cuda_runtime.h>
#include <cuda_bf16.h>
#include <cstdint>

#define NB    8
#define NPOS  1024
#define CIN   256
#define HEADS 8
#define DH    64
#define AD    512
#define COUT  256
#define QK_SCALE 0.125f
#define GN_EPS 1e-5f

// ---------------------------------------------------------------------------
// helpers
// ---------------------------------------------------------------------------
__device__ __forceinline__ uint32_t smem_u32(const void* p) {
    uint32_t a;
    asm("{ .reg .u64 t; cvta.to.shared.u64 t, %1; cvt.u32.u64 %0, t; }" : "=r"(a) : "l"(p));
    return a;
}

__device__ __forceinline__ void split_pair(float a, float b, uint32_t& hi, uint32_t& lo)
{
    __nv_bfloat16 ah = __float2bfloat16(a);
    __nv_bfloat16 bh = __float2bfloat16(b);
    float al = a - __bfloat162float(ah);
    float bl = b - __bfloat162float(bh);
    __nv_bfloat16 alh = __float2bfloat16(al);
    __nv_bfloat16 blh = __float2bfloat16(bl);
    hi = ((uint32_t)__bfloat16_as_ushort(bh)  << 16) | (uint32_t)__bfloat16_as_ushort(ah);
    lo = ((uint32_t)__bfloat16_as_ushort(blh) << 16) | (uint32_t)__bfloat16_as_ushort(alh);
}

__device__ __forceinline__ void mma16816(float* c, const uint32_t* a, const uint32_t* b)
{
    asm volatile("mma.sync.aligned.m16n8k16.row.col.f32.bf16.bf16.f32 "
        "{%0,%1,%2,%3},{%4,%5,%6,%7},{%8,%9},{%0,%1,%2,%3};"
        : "+f"(c[0]), "+f"(c[1]), "+f"(c[2]), "+f"(c[3])
        : "r"(a[0]), "r"(a[1]), "r"(a[2]), "r"(a[3]), "r"(b[0]), "r"(b[1]));
}

__device__ __forceinline__ void ldsm4(uint32_t* r, uint32_t addr)
{
    asm volatile("ldmatrix.sync.aligned.m8n8.x4.shared.b16 {%0,%1,%2,%3}, [%4];"
        : "=r"(r[0]), "=r"(r[1]), "=r"(r[2]), "=r"(r[3]) : "r"(addr));
}
__device__ __forceinline__ void ldsm4t(uint32_t* r, uint32_t addr)
{
    asm volatile("ldmatrix.sync.aligned.m8n8.x4.trans.shared.b16 {%0,%1,%2,%3}, [%4];"
        : "=r"(r[0]), "=r"(r[1]), "=r"(r[2]), "=r"(r[3]) : "r"(addr));
}

__device__ __forceinline__ void cp16(uint32_t dst, const void* src)
{
    asm volatile("cp.async.cg.shared.global [%0], [%1], 16;" :: "r"(dst), "l"(src));
}

// ---- smem tile helpers (still used by out_mma) ----
__device__ __forceinline__ uint32_t sw_addr(uint32_t base, int row, int ch) {
    return base + row * 128 + ((ch ^ (row & 7)) << 4);
}
__device__ __forceinline__ uint32_t afragT128_addr(uint32_t base, int k0, int m0, int lane) {
    int row = k0 + (lane & 7) + ((lane >> 4) & 1) * 8;
    int ch  = (m0 >> 3) + ((lane >> 3) & 1);
    return sw_addr(base, row, ch);
}
__device__ __forceinline__ uint32_t swp_off(int lrow, int ch) {
    int prow = lrow >> 1;
    int cp = ((lrow & 1) << 2) | ch;
    return (uint32_t)(prow * 128 + ((cp ^ (prow & 7)) << 4));
}
__device__ __forceinline__ uint32_t bfragP_addr(uint32_t base, int n0, int kc, int lane) {
    int lrow = n0 + (lane & 7) + ((lane >> 4) & 1) * 8;
    int ch   = 2 * kc + ((lane >> 3) & 1);
    return base + swp_off(lrow, ch);
}

// ---------------------------------------------------------------------------
// Scratch globals — fragment-packed operands
//   A-frag (m,k): lane=(m&7)*4+((k&7)>>1), reg=((m&8)>>3)|((k&8)>>2)
//   B-frag (n,k): lane=(n&7)*4+((k&7)>>1), reg=((k&8)>>3)|((n&8)>>2)
// ---------------------------------------------------------------------------
__device__ uint4 g_Xfh[512 * 16 * 32];          // X A-frags [mt][kcg][lane]
__device__ uint4 g_Xfl[512 * 16 * 32];
__device__ uint4 g_Wqfh[96 * 16 * 32];          // w_qkv B-frags [nt][kcg][lane]
__device__ uint4 g_Wqfl[96 * 16 * 32];
__device__ __nv_bfloat16 g_Woh[COUT * AD];      // w_out [d][ch] (out_mma smem path)
__device__ __nv_bfloat16 g_Wol[COUT * AD];
// Attention operands, fragment-packed:
__device__ uint4 g_Qfh[64 * 64 * 4 * 32];       // Q A-frags [bh][mt(64)][kcg(4)][lane]
__device__ uint4 g_Qfl[64 * 64 * 4 * 32];
__device__ uint4 g_Kfh[64 * 64 * 4 * 32];       // K B-frags [bh][nt=key/16][kcg=ch/16][lane]
__device__ uint4 g_Kfl[64 * 64 * 4 * 32];
__device__ uint4 g_Vfh[64 * 4 * 64 * 32];       // V B-frags [bh][vt=ch/16][kcg=key/16][lane]
__device__ uint4 g_Vfl[64 * 4 * 64 * 32];
__device__ __nv_bfloat16 g_A2h[NB * AD * NPOS]; // [b][ch][pos]
__device__ __nv_bfloat16 g_A2l[NB * AD * NPOS];
__device__ float g_Y[NB * NPOS * COUT];
__device__ float g_part[1024];
__device__ float g_stats[2 * NB];

// ---------------------------------------------------------------------------
// Kernel 0a: X -> split bf16 A-frag packed
// ---------------------------------------------------------------------------
__global__ __launch_bounds__(256) void conv_x_kernel(const float* __restrict__ X)
{
    int idx4 = blockIdx.x * 256 + threadIdx.x;
    int m  = idx4 >> 6;
    int c4 = (idx4 & 63) * 4;
    float4 v = reinterpret_cast<const float4*>(X)[idx4];

    uint32_t* Xh = reinterpret_cast<uint32_t*>(g_Xfh);
    uint32_t* Xl = reinterpret_cast<uint32_t*>(g_Xfl);

    int mt = m >> 4;
    #pragma unroll
    for (int p = 0; p < 2; p++) {
        int c = c4 + p * 2;
        float va = p ? v.z : v.x;
        float vb = p ? v.w : v.y;
        uint32_t hi, lo;
        split_pair(va, vb, hi, lo);
        int kcg = c >> 4;
        int lane = (m & 7) * 4 + ((c & 7) >> 1);
        int reg  = ((m & 8) >> 3) | ((c & 8) >> 2);
        size_t off = ((size_t)(mt * 16 + kcg) * 32 + lane) * 4 + reg;
        Xh[off] = hi;
        Xl[off] = lo;
    }
}

// ---------------------------------------------------------------------------
// Kernel 0b: weight transpose + split.
// which=0: w_qkv -> B-frag packed; which=1: w_out -> linear [d][ch]
// ---------------------------------------------------------------------------
__global__ void conv_w_kernel(const float* __restrict__ src, int K, int N, int which)
{
    __shared__ float tile[32][33];
    int n0 = blockIdx.x * 32;
    int k0 = blockIdx.y * 32;
    int tx = threadIdx.x, ty = threadIdx.y;
    tile[ty][tx] = src[(size_t)(k0 + ty) * N + n0 + tx];
    __syncthreads();
    if (tx < 16) {
        uint32_t hi, lo;
        split_pair(tile[2*tx][ty], tile[2*tx+1][ty], hi, lo);
        int k = k0 + 2 * tx;
        int n = n0 + ty;
        if (which == 0) {
            uint32_t* Wh = reinterpret_cast<uint32_t*>(g_Wqfh);
            uint32_t* Wl = reinterpret_cast<uint32_t*>(g_Wqfl);
            int nt = n >> 4, kcg = k >> 4;
            int lane = (n & 7) * 4 + ((k & 7) >> 1);
            int reg  = ((k & 8) >> 3) | ((n & 8) >> 2);
            size_t off = ((size_t)(nt * 16 + kcg) * 32 + lane) * 4 + reg;
            Wh[off] = hi;
            Wl[off] = lo;
        } else {
            size_t off = (size_t)n * K + k;
            *reinterpret_cast<uint32_t*>(&g_Woh[off]) = hi;
            *reinterpret_cast<uint32_t*>(&g_Wol[off]) = lo;
        }
    }
}

// ---------------------------------------------------------------------------
// Kernel 1: QKV GEMM — no smem (R9 mainloop). Epilogue now writes Q/K/V in
// FRAGMENT-PACKED layouts (Q: A-frag; K,V: B-frag) with coalesced uint4 stores.
// ---------------------------------------------------------------------------
__global__ __launch_bounds__(128, 3) void qkv_mma_kernel()
{
    const int tid = threadIdx.x, lane = tid & 31, wid = tid >> 5;
    const int n_blk = blockIdx.x * 64;
    const int m_blk = blockIdx.y * 128;
    const int mw = (wid >> 1) * 64;
    const int nw = (wid & 1) * 32;
    const int g = lane >> 2;

    const int mt0 = (m_blk + mw) >> 4;
    const int nt0 = (n_blk + nw) >> 4;

    float acc[4][4][4];
    #pragma unroll
    for (int i = 0; i < 4; i++)
        #pragma unroll
        for (int j = 0; j < 4; j++)
            #pragma unroll
            for (int k = 0; k < 4; k++) acc[i][j][k] = 0.0f;

    uint4 ahf[2][4], alf[2][4], bhf[2][2], blf[2][2];

    const uint4* Xh = g_Xfh; const uint4* Xl = g_Xfl;
    const uint4* Wh = g_Wqfh; const uint4* Wl = g_Wqfl;

    #pragma unroll
    for (int mf = 0; mf < 4; mf++) {
        size_t o = ((size_t)(mt0 + mf) * 16 + 0) * 32 + lane;
        ahf[0][mf] = Xh[o]; alf[0][mf] = Xl[o];
    }
    #pragma unroll
    for (int nf = 0; nf < 2; nf++) {
        size_t o = ((size_t)(nt0 + nf) * 16 + 0) * 32 + lane;
        bhf[0][nf] = Wh[o]; blf[0][nf] = Wl[o];
    }

    #pragma unroll
    for (int kcg = 0; kcg < 16; kcg++) {
        const int cur = kcg & 1;
        if (kcg < 15) {
            const int nxt = cur ^ 1;
            #pragma unroll
            for (int mf = 0; mf < 4; mf++) {
                size_t o = ((size_t)(mt0 + mf) * 16 + (kcg + 1)) * 32 + lane;
                ahf[nxt][mf] = Xh[o]; alf[nxt][mf] = Xl[o];
            }
            #pragma unroll
            for (int nf = 0; nf < 2; nf++) {
                size_t o = ((size_t)(nt0 + nf) * 16 + (kcg + 1)) * 32 + lane;
                bhf[nxt][nf] = Wh[o]; blf[nxt][nf] = Wl[o];
            }
        }
        #pragma unroll
        for (int mf = 0; mf < 4; mf++) {
            const uint32_t* a = reinterpret_cast<const uint32_t*>(&ahf[cur][mf]);
            #pragma unroll
            for (int nf = 0; nf < 2; nf++) {
                const uint32_t* b = reinterpret_cast<const uint32_t*>(&bhf[cur][nf]);
                mma16816(acc[mf][2*nf],   a, b + 0);
                mma16816(acc[mf][2*nf+1], a, b + 2);
            }
        }
        #pragma unroll
        for (int mf = 0; mf < 4; mf++) {
            const uint32_t* a = reinterpret_cast<const uint32_t*>(&ahf[cur][mf]);
            #pragma unroll
            for (int nf = 0; nf < 2; nf++) {
                const uint32_t* b = reinterpret_cast<const uint32_t*>(&blf[cur][nf]);
                mma16816(acc[mf][2*nf],   a, b + 0);
                mma16816(acc[mf][2*nf+1], a, b + 2);
            }
        }
        #pragma unroll
        for (int mf = 0; mf < 4; mf++) {
            const uint32_t* a = reinterpret_cast<const uint32_t*>(&alf[cur][mf]);
            #pragma unroll
            for (int nf = 0; nf < 2; nf++) {
                const uint32_t* b = reinterpret_cast<const uint32_t*>(&bhf[cur][nf]);
                mma16816(acc[mf][2*nf],   a, b + 0);
                mma16816(acc[mf][2*nf+1], a, b + 2);
            }
        }
    }

    // ---- epilogue: fragment-packed Q / K / V ----
    const int which = n_blk >> 9;
    const int h = (n_blk >> 6) & 7;

    if (which == 0) {
        // Q: A-frag packed, scaled. uint4 regs: [0]=j0 rows g, [1]=j0 rows g+8,
        // [2]=j1 rows g, [3]=j1 rows g+8.
        #pragma unroll
        for (int mf = 0; mf < 4; mf++) {
            int r0 = m_blk + mw + mf*16 + g;
            int bh = (r0 >> 10) * HEADS + h;
            int mt = (r0 & 1023) >> 4;
            #pragma unroll
            for (int kco = 0; kco < 2; kco++) {
                int j0 = 2*kco, j1 = j0 + 1;
                uint32_t h0,l0,h1,l1,h2,l2,h3,l3;
                split_pair(acc[mf][j0][0]*QK_SCALE, acc[mf][j0][1]*QK_SCALE, h0, l0);
                split_pair(acc[mf][j0][2]*QK_SCALE, acc[mf][j0][3]*QK_SCALE, h1, l1);
                split_pair(acc[mf][j1][0]*QK_SCALE, acc[mf][j1][1]*QK_SCALE, h2, l2);
                split_pair(acc[mf][j1][2]*QK_SCALE, acc[mf][j1][3]*QK_SCALE, h3, l3);
                int kcg = (nw >> 4) + kco;
                size_t o = ((size_t)(bh*64 + mt)*4 + kcg)*32 + lane;
                g_Qfh[o] = make_uint4(h0, h1, h2, h3);
                g_Qfl[o] = make_uint4(l0, l1, l2, l3);
            }
        }
    } else if (which == 1) {
        // K: B-frag packed. uint4 regs: [0]=j0 keys g, [1]=j1 keys g,
        // [2]=j0 keys g+8, [3]=j1 keys g+8.
        #pragma unroll
        for (int mf = 0; mf < 4; mf++) {
            int r0 = m_blk + mw + mf*16 + g;
            int bh = (r0 >> 10) * HEADS + h;
            int nt = (r0 & 1023) >> 4;
            #pragma unroll
            for (int kco = 0; kco < 2; kco++) {
                int j0 = 2*kco, j1 = j0 + 1;
                uint32_t h0,l0,h1,l1,h2,l2,h3,l3;
                split_pair(acc[mf][j0][0], acc[mf][j0][1], h0, l0);
                split_pair(acc[mf][j1][0], acc[mf][j1][1], h1, l1);
                split_pair(acc[mf][j0][2], acc[mf][j0][3], h2, l2);
                split_pair(acc[mf][j1][2], acc[mf][j1][3], h3, l3);
                int kcg = (nw >> 4) + kco;
                size_t o = ((size_t)(bh*64 + nt)*4 + kcg)*32 + lane;
                g_Kfh[o] = make_uint4(h0, h1, h2, h3);
                g_Kfl[o] = make_uint4(l0, l1, l2, l3);
            }
        }
    } else {
        // V: B-frag packed over key pairs (needs partner-row values via shfl).
        // Thread (g,tig) holds (key=r0, ch=c..c+1); key pair (even,odd) spans
        // threads g and g^1 (lane^4). Even thread emits channel c, odd c+1.
        const int tigl = lane & 3;
        int odd = g & 1;
        #pragma unroll
        for (int mf = 0; mf < 4; mf++) {
            int r0 = m_blk + mw + mf*16 + g;
            int bh = (r0 >> 10) * HEADS + h;
            int kcgv = (r0 & 1023) >> 4;
            #pragma unroll
            for (int kco = 0; kco < 2; kco++) {
                int j0 = 2*kco, j1 = j0 + 1;
                float o00 = __shfl_xor_sync(0xffffffffu, acc[mf][j0][0], 4);
                float o01 = __shfl_xor_sync(0xffffffffu, acc[mf][j0][1], 4);
                float o02 = __shfl_xor_sync(0xffffffffu, acc[mf][j0][2], 4);
                float o03 = __shfl_xor_sync(0xffffffffu, acc[mf][j0][3], 4);
                float o10 = __shfl_xor_sync(0xffffffffu, acc[mf][j1][0], 4);
                float o11 = __shfl_xor_sync(0xffffffffu, acc[mf][j1][1], 4);
                float o12 = __shfl_xor_sync(0xffffffffu, acc[mf][j1][2], 4);
                float o13 = __shfl_xor_sync(0xffffffffu, acc[mf][j1][3], 4);
                // (vE, vO) per (j, keypair-half)
                float aE = odd ? o11 : acc[mf][j0][0];
                float aO = odd ? acc[mf][j0][1] : o00;
                float bE = odd ? o13 : acc[mf][j0][2];
                float bO = odd ? acc[mf][j0][3] : o02;
                // fix: the shuffles above must match channel: for odd thread use j0's partner [1]
                aE = odd ? o01 : acc[mf][j0][0];
                aO = odd ? acc[mf][j0][1] : o00;
                bE = odd ? o03 : acc[mf][j0][2];
                bO = odd ? acc[mf][j0][3] : o02;
                float cE = odd ? o11 : acc[mf][j1][0];
                float cO = odd ? acc[mf][j1][1] : o10;
                float dE = odd ? o13 : acc[mf][j1][2];
                float dO = odd ? acc[mf][j1][3] : o12;
                uint32_t h0,l0,h1,l1,h2,l2,h3,l3;
                split_pair(aE, aO, h0, l0);   // reg0: j0, keys lo
                split_pair(bE, bO, h1, l1);   // reg1: j0, keys hi
                split_pair(cE, cO, h2, l2);   // reg2: j1, keys lo
                split_pair(dE, dO, h3, l3);   // reg3: j1, keys hi
                int lane_t = tigl*8 + odd*4 + (g >> 1);
                int vt = (nw >> 4) + kco;
                size_t o = ((size_t)(bh*4 + vt)*64 + kcgv)*32 + lane_t;
                g_Vfh[o] = make_uint4(h0, h1, h2, h3);
                g_Vfl[o] = make_uint4(l0, l1, l2, l3);
            }
        }
    }
}

// ---------------------------------------------------------------------------
// Kernel 2: attention — NO SMEM. All operands via coalesced LDG.128 from
// fragment-packed Q/K/V (L2-resident). Zero barriers.
// ---------------------------------------------------------------------------
__global__ __launch_bounds__(128) void attn_mma_kernel()
{
    const int tid  = threadIdx.x;
    const int lane = tid & 31;
    const int wid  = tid >> 5;
    const int bh   = blockIdx.y;
    const int qb   = blockIdx.x * 64 + wid * 16;
    const int g    = lane >> 2;
    const int tig  = lane & 3;

    // Q fragments (packed)
    uint4 qh4[4], ql4[4];
    {
        int mt = qb >> 4;
        #pragma unroll
        for (int kcg = 0; kcg < 4; kcg++) {
            size_t o = ((size_t)(bh*64 + mt)*4 + kcg)*32 + lane;
            qh4[kcg] = g_Qfh[o];
            ql4[kcg] = g_Qfl[o];
        }
    }

    float oc[8][4];
    #pragma unroll
    for (int i = 0; i < 8; i++)
        #pragma unroll
        for (int j = 0; j < 4; j++) oc[i][j] = 0.0f;
    float lsum0 = 0.0f, lsum1 = 0.0f;

    for (int kt = 0; kt < 16; kt++) {
        // ---- S = Qh*Kh + Qh*Kl + Ql*Kh ----
        float s[8][4];
        #pragma unroll
        for (int i = 0; i < 8; i++)
            #pragma unroll
            for (int j = 0; j < 4; j++) s[i][j] = 0.0f;

        #pragma unroll
        for (int kcg = 0; kcg < 4; kcg++) {
            uint4 kh4[4], kl4[4];
            #pragma unroll
            for (int np = 0; np < 4; np++) {
                size_t o = ((size_t)(bh*64 + kt*4 + np)*4 + kcg)*32 + lane;
                kh4[np] = g_Kfh[o];
                kl4[np] = g_Kfl[o];
            }
            const uint32_t* qh = reinterpret_cast<const uint32_t*>(&qh4[kcg]);
            const uint32_t* ql = reinterpret_cast<const uint32_t*>(&ql4[kcg]);
            #pragma unroll
            for (int np = 0; np < 4; np++) {
                const uint32_t* b = reinterpret_cast<const uint32_t*>(&kh4[np]);
                mma16816(s[2*np],   qh, b + 0);
                mma16816(s[2*np+1], qh, b + 2);
            }
            #pragma unroll
            for (int np = 0; np < 4; np++) {
                const uint32_t* b = reinterpret_cast<const uint32_t*>(&kl4[np]);
                mma16816(s[2*np],   qh, b + 0);
                mma16816(s[2*np+1], qh, b + 2);
            }
            #pragma unroll
            for (int np = 0; np < 4; np++) {
                const uint32_t* b = reinterpret_cast<const uint32_t*>(&kh4[np]);
                mma16816(s[2*np],   ql, b + 0);
                mma16816(s[2*np+1], ql, b + 2);
            }
        }

        // ---- exp + pack P ----
        uint32_t ph[4][4], pl[4][4];
        #pragma unroll
        for (int np = 0; np < 4; np++) {
            float p0[4], p1[4];
            #pragma unroll
            for (int j = 0; j < 4; j++) {
                p0[j] = __expf(s[2*np][j]);
                p1[j] = __expf(s[2*np+1][j]);
            }
            lsum0 += p0[0] + p0[1] + p1[0] + p1[1];
            lsum1 += p0[2] + p0[3] + p1[2] + p1[3];
            split_pair(p0[0], p0[1], ph[np][0], pl[np][0]);
            split_pair(p0[2], p0[3], ph[np][1], pl[np][1]);
            split_pair(p1[0], p1[1], ph[np][2], pl[np][2]);
            split_pair(p1[2], p1[3], ph[np][3], pl[np][3]);
        }

        // ---- O += Ph*Vh + Ph*Vl + Pl*Vh ----
        #pragma unroll
        for (int jc = 0; jc < 4; jc++) {
            uint4 vh4[4], vl4[4];
            #pragma unroll
            for (int vp = 0; vp < 4; vp++) {
                size_t o = ((size_t)(bh*4 + vp)*64 + kt*4 + jc)*32 + lane;
                vh4[vp] = g_Vfh[o];
                vl4[vp] = g_Vfl[o];
            }
            #pragma unroll
            for (int vp = 0; vp < 4; vp++) {
                const uint32_t* b = reinterpret_cast<const uint32_t*>(&vh4[vp]);
                mma16816(oc[2*vp],   ph[jc], b + 0);
                mma16816(oc[2*vp+1], ph[jc], b + 2);
            }
            #pragma unroll
            for (int vp = 0; vp < 4; vp++) {
                const uint32_t* b = reinterpret_cast<const uint32_t*>(&vl4[vp]);
                mma16816(oc[2*vp],   ph[jc], b + 0);
                mma16816(oc[2*vp+1], ph[jc], b + 2);
            }
            #pragma unroll
            for (int vp = 0; vp < 4; vp++) {
                const uint32_t* b = reinterpret_cast<const uint32_t*>(&vh4[vp]);
                mma16816(oc[2*vp],   pl[jc], b + 0);
                mma16816(oc[2*vp+1], pl[jc], b + 2);
            }
        }
    }

    lsum0 += __shfl_xor_sync(0xffffffffu, lsum0, 1);
    lsum0 += __shfl_xor_sync(0xffffffffu, lsum0, 2);
    lsum1 += __shfl_xor_sync(0xffffffffu, lsum1, 1);
    lsum1 += __shfl_xor_sync(0xffffffffu, lsum1, 2);
    float inv0 = 1.0f / lsum0;
    float inv1 = 1.0f / lsum1;

    int b = bh >> 3, h = bh & 7;
    int q0 = qb + g, q1 = qb + g + 8;
    size_t row0 = ((size_t)(b * AD + h * 64 + (q0 >> 4))) * NPOS + ((q0 & 15) << 6);
    size_t row1 = ((size_t)(b * AD + h * 64 + (q1 >> 4))) * NPOS + ((q1 & 15) << 6);
    #pragma unroll
    for (int ct = 0; ct < 8; ct++) {
        int c = ct * 8 + tig * 2;
        uint32_t hi, lo;
        split_pair(oc[ct][0] * inv0, oc[ct][1] * inv0, hi, lo);
        *reinterpret_cast<uint32_t*>(&g_A2h[row0 + c]) = hi;
        *reinterpret_cast<uint32_t*>(&g_A2l[row0 + c]) = lo;
        split_pair(oc[ct][2] * inv1, oc[ct][3] * inv1, hi, lo);
        *reinterpret_cast<uint32_t*>(&g_A2h[row1 + c]) = hi;
        *reinterpret_cast<uint32_t*>(&g_A2l[row1 + c]) = lo;
    }
}

// ---------------------------------------------------------------------------
// Kernel 3: out GEMM + fused GN partials (unchanged R9)
// ---------------------------------------------------------------------------
__global__ __launch_bounds__(128, 4) void out_mma_kernel(const float* __restrict__ bout)
{
    extern __shared__ uint8_t dyn_o[];
    const uint32_t sbase = smem_u32(dyn_o);

    const int tid = threadIdx.x, lane = tid & 31, wid = tid >> 5;
    const int m_blk = blockIdx.x * 64;
    const int n_blk = blockIdx.y * 64;
    const int bb = blockIdx.z;
    const int mw = (wid >> 1) * 32;
    const int nw = (wid & 1) * 32;
    const int g = lane >> 2, tig = lane & 3;

    float acc[2][4][4];
    #pragma unroll
    for (int i = 0; i < 2; i++)
        #pragma unroll
        for (int j = 0; j < 4; j++)
            #pragma unroll
            for (int k = 0; k < 4; k++) acc[i][j][k] = 0.0f;

    const __nv_bfloat16* A2h = g_A2h + (size_t)bb * AD * NPOS;
    const __nv_bfloat16* A2l = g_A2l + (size_t)bb * AD * NPOS;

    auto preload = [&](int ks, int buf) {
        uint32_t b0 = sbase + buf * 16384;
        int k0 = ks * 32;
        #pragma unroll
        for (int i = 0; i < 2; i++) {
            int idx = i * 128 + tid;
            int row = idx >> 3, ch = idx & 7;
            uint32_t off = (uint32_t)(row * 128 + ((ch ^ (row & 7)) << 4));
            size_t go = (size_t)(k0 + row) * NPOS + m_blk + ch * 8;
            cp16(b0 + off,        A2h + go);
            cp16(b0 + 4096 + off, A2l + go);
        }
        #pragma unroll
        for (int i = 0; i < 2; i++) {
            int idx = i * 128 + tid;
            int lrow = idx >> 2, ch = idx & 3;
            uint32_t off = swp_off(lrow, ch);
            size_t go = (size_t)(n_blk + lrow) * AD + k0 + ch * 8;
            cp16(b0 + 8192 + off,  g_Woh + go);
            cp16(b0 + 12288 + off, g_Wol + go);
        }
        asm volatile("cp.async.commit_group;" ::: "memory");
    };

    preload(0, 0);

    for (int s = 0; s < 16; s++) {
        asm volatile("cp.async.wait_group 0;" ::: "memory");
        __syncthreads();
        if (s < 15) preload(s + 1, (s + 1) & 1);

        uint32_t b0 = sbase + (s & 1) * 16384;
        const uint32_t sAh = b0, sAl = b0 + 4096, sBh = b0 + 8192, sBl = b0 + 12288;

        #pragma unroll
        for (int kc = 0; kc < 2; kc++) {
            uint32_t bh0[4], bl0[4], bh1[4], bl1[4];
            ldsm4(bh0, bfragP_addr(sBh, nw,      kc, lane));
            ldsm4(bh1, bfragP_addr(sBh, nw + 16, kc, lane));
            ldsm4(bl0, bfragP_addr(sBl, nw,      kc, lane));
            ldsm4(bl1, bfragP_addr(sBl, nw + 16, kc, lane));
            #pragma unroll
            for (int mf = 0; mf < 2; mf++) {
                uint32_t ah[4], al[4];
                ldsm4t(ah, afragT128_addr(sAh, kc*16, mw + mf*16, lane));
                ldsm4t(al, afragT128_addr(sAl, kc*16, mw + mf*16, lane));
                mma16816(acc[mf][0], ah, bh0 + 0); mma16816(acc[mf][1], ah, bh0 + 2);
                mma16816(acc[mf][2], ah, bh1 + 0); mma16816(acc[mf][3], ah, bh1 + 2);
                mma16816(acc[mf][0], ah, bl0 + 0); mma16816(acc[mf][1], ah, bl0 + 2);
                mma16816(acc[mf][2], ah, bl1 + 0); mma16816(acc[mf][3], ah, bl1 + 2);
                mma16816(acc[mf][0], al, bh0 + 0); mma16816(acc[mf][1], al, bh0 + 2);
                mma16816(acc[mf][2], al, bh1 + 0); mma16816(acc[mf][3], al, bh1 + 2);
            }
        }
    }

    float psum = 0.0f, psq = 0.0f;
    #pragma unroll
    for (int mf = 0; mf < 2; mf++) {
        int r0 = m_blk + mw + mf*16 + g;
        #pragma unroll
        for (int j = 0; j < 4; j++) {
            int d = n_blk + nw + j * 8 + tig * 2;
            float2 bv = *reinterpret_cast<const float2*>(&bout[d]);
            float2 v0 = make_float2(acc[mf][j][0] + bv.x, acc[mf][j][1] + bv.y);
            float2 v1 = make_float2(acc[mf][j][2] + bv.x, acc[mf][j][3] + bv.y);
            *reinterpret_cast<float2*>(&g_Y[((size_t)bb*NPOS + r0)*COUT + d]) = v0;
            *reinterpret_cast<float2*>(&g_Y[((size_t)bb*NPOS + r0 + 8)*COUT + d]) = v1;
            psum += v0.x + v0.y + v1.x + v1.y;
            psq  += v0.x*v0.x + v0.y*v0.y + v1.x*v1.x + v1.y*v1.y;
        }
    }

    __syncthreads();
    float* rs  = reinterpret_cast<float*>(dyn_o);
    float* rss = rs + 128;
    rs[tid] = psum; rss[tid] = psq;
    __syncthreads();
    for (int st = 64; st > 0; st >>= 1) {
        if (tid < st) { rs[tid] += rs[tid + st]; rss[tid] += rss[tid + st]; }
        __syncthreads();
    }
    if (tid == 0) {
        int p = bb * 64 + blockIdx.x * 4 + blockIdx.y;
        g_part[2*p]   = rs[0];
        g_part[2*p+1] = rss[0];
    }
}

// ---------------------------------------------------------------------------
// GN final + normalize
// ---------------------------------------------------------------------------
__global__ void gn_final_kernel()
{
    int b = threadIdx.x;
    if (b < NB) {
        float s = 0.0f, ss = 0.0f;
        #pragma unroll
        for (int i = 0; i < 64; i++) {
            s  += g_part[2*(b*64 + i)];
            ss += g_part[2*(b*64 + i) + 1];
        }
        const float inv_n = 1.0f / (float)(NPOS * COUT);
        float mean = s * inv_n;
        float var  = ss * inv_n - mean * mean;
        g_stats[2*b]     = mean;
        g_stats[2*b + 1] = rsqrtf(var + GN_EPS);
    }
}

__global__ __launch_bounds__(256) void gn_norm_kernel(
    const float* __restrict__ gamma, const float* __restrict__ beta,
    float* __restrict__ out)
{
    int idx4 = blockIdx.x * 256 + threadIdx.x;
    int b  = idx4 >> 16;
    int d4 = idx4 & 63;

    float mean = g_stats[2*b];
    float rstd = g_stats[2*b + 1];

    float4 y  = reinterpret_cast<const float4*>(g_Y)[idx4];
    float4 g  = reinterpret_cast<const float4*>(gamma)[d4];
    float4 be = reinterpret_cast<const float4*>(beta)[d4];

    float4 r;
    r.x = (y.x - mean) * rstd * g.x + be.x;
    r.y = (y.y - mean) * rstd * g.y + be.y;
    r.z = (y.z - mean) * rstd * g.z + be.z;
    r.w = (y.w - mean) * rstd * g.w + be.w;
    reinterpret_cast<float4*>(out)[idx4] = r;
}

// ---------------------------------------------------------------------------
extern "C" void kernel_launch(void* const* d_in, const int* in_sizes, int n_in,
                              void* d_out, int out_size)
{
    const float* x      = (const float*)d_in[0];
    const float* w_qkv  = (const float*)d_in[1];
    const float* w_out  = (const float*)d_in[2];
    const float* b_out  = (const float*)d_in[3];
    const float* gamma  = (const float*)d_in[4];
    const float* beta   = (const float*)d_in[5];
    float* out = (float*)d_out;

    static int smem_set = 0;
    if (!smem_set) {
        cudaFuncSetAttribute(out_mma_kernel,
                             cudaFuncAttributeMaxDynamicSharedMemorySize, 32768);
        smem_set = 1;
    }

    conv_x_kernel<<<2048, 256>>>(x);
    conv_w_kernel<<<dim3(48, 8),  dim3(32, 32)>>>(w_qkv, CIN, 3*AD, 0);
    conv_w_kernel<<<dim3(8, 16),  dim3(32, 32)>>>(w_out, AD, COUT, 1);
    qkv_mma_kernel<<<dim3(24, 64), 128>>>();
    attn_mma_kernel<<<dim3(16, 64), 128>>>();
    out_mma_kernel<<<dim3(16, 4, 8), 128, 32768>>>(b_out);
    gn_final_kernel<<<1, 32>>>();
    gn_norm_kernel<<<2048, 256>>>(gamma, beta, out);
}

// round 11
// speedup vs baseline: 1.2730x; 1.2730x over previous
#include <cuda_runtime.h>
#include <cuda_bf16.h>
#include <cstdint>

#define NB    8
#define NPOS  1024
#define CIN   256
#define HEADS 8
#define DH    64
#define AD    512
#define COUT  256
#define QK_SCALE 0.125f
#define GN_EPS 1e-5f

// ---------------------------------------------------------------------------
// helpers
// ---------------------------------------------------------------------------
__device__ __forceinline__ uint32_t smem_u32(const void* p) {
    uint32_t a;
    asm("{ .reg .u64 t; cvta.to.shared.u64 t, %1; cvt.u32.u64 %0, t; }" : "=r"(a) : "l"(p));
    return a;
}

__device__ __forceinline__ void split_pair(float a, float b, uint32_t& hi, uint32_t& lo)
{
    __nv_bfloat16 ah = __float2bfloat16(a);
    __nv_bfloat16 bh = __float2bfloat16(b);
    float al = a - __bfloat162float(ah);
    float bl = b - __bfloat162float(bh);
    __nv_bfloat16 alh = __float2bfloat16(al);
    __nv_bfloat16 blh = __float2bfloat16(bl);
    hi = ((uint32_t)__bfloat16_as_ushort(bh)  << 16) | (uint32_t)__bfloat16_as_ushort(ah);
    lo = ((uint32_t)__bfloat16_as_ushort(blh) << 16) | (uint32_t)__bfloat16_as_ushort(alh);
}

__device__ __forceinline__ void mma16816(float* c, const uint32_t* a, const uint32_t* b)
{
    asm volatile("mma.sync.aligned.m16n8k16.row.col.f32.bf16.bf16.f32 "
        "{%0,%1,%2,%3},{%4,%5,%6,%7},{%8,%9},{%0,%1,%2,%3};"
        : "+f"(c[0]), "+f"(c[1]), "+f"(c[2]), "+f"(c[3])
        : "r"(a[0]), "r"(a[1]), "r"(a[2]), "r"(a[3]), "r"(b[0]), "r"(b[1]));
}

__device__ __forceinline__ void ldsm4(uint32_t* r, uint32_t addr)
{
    asm volatile("ldmatrix.sync.aligned.m8n8.x4.shared.b16 {%0,%1,%2,%3}, [%4];"
        : "=r"(r[0]), "=r"(r[1]), "=r"(r[2]), "=r"(r[3]) : "r"(addr));
}
__device__ __forceinline__ void ldsm4t(uint32_t* r, uint32_t addr)
{
    asm volatile("ldmatrix.sync.aligned.m8n8.x4.trans.shared.b16 {%0,%1,%2,%3}, [%4];"
        : "=r"(r[0]), "=r"(r[1]), "=r"(r[2]), "=r"(r[3]) : "r"(addr));
}

__device__ __forceinline__ void cp16(uint32_t dst, const void* src)
{
    asm volatile("cp.async.cg.shared.global [%0], [%1], 16;" :: "r"(dst), "l"(src));
}

__device__ __forceinline__ uint4 lds128(uint32_t addr)
{
    uint4 v;
    asm volatile("ld.shared.v4.u32 {%0,%1,%2,%3}, [%4];"
        : "=r"(v.x), "=r"(v.y), "=r"(v.z), "=r"(v.w) : "r"(addr));
    return v;
}

// ---- smem tile helpers (out_mma path) ----
__device__ __forceinline__ uint32_t sw_addr(uint32_t base, int row, int ch) {
    return base + row * 128 + ((ch ^ (row & 7)) << 4);
}
__device__ __forceinline__ uint32_t afragT128_addr(uint32_t base, int k0, int m0, int lane) {
    int row = k0 + (lane & 7) + ((lane >> 4) & 1) * 8;
    int ch  = (m0 >> 3) + ((lane >> 3) & 1);
    return sw_addr(base, row, ch);
}
__device__ __forceinline__ uint32_t swp_off(int lrow, int ch) {
    int prow = lrow >> 1;
    int cp = ((lrow & 1) << 2) | ch;
    return (uint32_t)(prow * 128 + ((cp ^ (prow & 7)) << 4));
}
__device__ __forceinline__ uint32_t bfragP_addr(uint32_t base, int n0, int kc, int lane) {
    int lrow = n0 + (lane & 7) + ((lane >> 4) & 1) * 8;
    int ch   = 2 * kc + ((lane >> 3) & 1);
    return base + swp_off(lrow, ch);
}

// ---------------------------------------------------------------------------
// Scratch globals — fragment-packed operands
// ---------------------------------------------------------------------------
__device__ uint4 g_Xfh[512 * 16 * 32];
__device__ uint4 g_Xfl[512 * 16 * 32];
__device__ uint4 g_Wqfh[96 * 16 * 32];
__device__ uint4 g_Wqfl[96 * 16 * 32];
__device__ __nv_bfloat16 g_Woh[COUT * AD];
__device__ __nv_bfloat16 g_Wol[COUT * AD];
__device__ uint4 g_Qfh[64 * 64 * 4 * 32];       // Q A-frags [bh][mt][kcg][lane]
__device__ uint4 g_Qfl[64 * 64 * 4 * 32];
__device__ uint4 g_Kfh[64 * 64 * 4 * 32];       // K B-frags [bh][nt][kcg][lane]
__device__ uint4 g_Kfl[64 * 64 * 4 * 32];
__device__ uint4 g_Vfh[64 * 4 * 64 * 32];       // V B-frags [bh][vt][kcg_key][lane]
__device__ uint4 g_Vfl[64 * 4 * 64 * 32];
__device__ __nv_bfloat16 g_A2h[NB * AD * NPOS];
__device__ __nv_bfloat16 g_A2l[NB * AD * NPOS];
__device__ float g_Y[NB * NPOS * COUT];
__device__ float g_part[1024];
__device__ float g_stats[2 * NB];

// ---------------------------------------------------------------------------
// Kernel 0a: X -> split bf16 A-frag packed
// ---------------------------------------------------------------------------
__global__ __launch_bounds__(256) void conv_x_kernel(const float* __restrict__ X)
{
    int idx4 = blockIdx.x * 256 + threadIdx.x;
    int m  = idx4 >> 6;
    int c4 = (idx4 & 63) * 4;
    float4 v = reinterpret_cast<const float4*>(X)[idx4];

    uint32_t* Xh = reinterpret_cast<uint32_t*>(g_Xfh);
    uint32_t* Xl = reinterpret_cast<uint32_t*>(g_Xfl);

    int mt = m >> 4;
    #pragma unroll
    for (int p = 0; p < 2; p++) {
        int c = c4 + p * 2;
        float va = p ? v.z : v.x;
        float vb = p ? v.w : v.y;
        uint32_t hi, lo;
        split_pair(va, vb, hi, lo);
        int kcg = c >> 4;
        int lane = (m & 7) * 4 + ((c & 7) >> 1);
        int reg  = ((m & 8) >> 3) | ((c & 8) >> 2);
        size_t off = ((size_t)(mt * 16 + kcg) * 32 + lane) * 4 + reg;
        Xh[off] = hi;
        Xl[off] = lo;
    }
}

// ---------------------------------------------------------------------------
// Kernel 0b: weight transpose + split.
// ---------------------------------------------------------------------------
__global__ void conv_w_kernel(const float* __restrict__ src, int K, int N, int which)
{
    __shared__ float tile[32][33];
    int n0 = blockIdx.x * 32;
    int k0 = blockIdx.y * 32;
    int tx = threadIdx.x, ty = threadIdx.y;
    tile[ty][tx] = src[(size_t)(k0 + ty) * N + n0 + tx];
    __syncthreads();
    if (tx < 16) {
        uint32_t hi, lo;
        split_pair(tile[2*tx][ty], tile[2*tx+1][ty], hi, lo);
        int k = k0 + 2 * tx;
        int n = n0 + ty;
        if (which == 0) {
            uint32_t* Wh = reinterpret_cast<uint32_t*>(g_Wqfh);
            uint32_t* Wl = reinterpret_cast<uint32_t*>(g_Wqfl);
            int nt = n >> 4, kcg = k >> 4;
            int lane = (n & 7) * 4 + ((k & 7) >> 1);
            int reg  = ((k & 8) >> 3) | ((n & 8) >> 2);
            size_t off = ((size_t)(nt * 16 + kcg) * 32 + lane) * 4 + reg;
            Wh[off] = hi;
            Wl[off] = lo;
        } else {
            size_t off = (size_t)n * K + k;
            *reinterpret_cast<uint32_t*>(&g_Woh[off]) = hi;
            *reinterpret_cast<uint32_t*>(&g_Wol[off]) = lo;
        }
    }
}

// ---------------------------------------------------------------------------
// Kernel 1: QKV GEMM — no smem; frag-packed epilogue (R10, unchanged).
// ---------------------------------------------------------------------------
__global__ __launch_bounds__(128, 3) void qkv_mma_kernel()
{
    const int tid = threadIdx.x, lane = tid & 31, wid = tid >> 5;
    const int n_blk = blockIdx.x * 64;
    const int m_blk = blockIdx.y * 128;
    const int mw = (wid >> 1) * 64;
    const int nw = (wid & 1) * 32;
    const int g = lane >> 2;

    const int mt0 = (m_blk + mw) >> 4;
    const int nt0 = (n_blk + nw) >> 4;

    float acc[4][4][4];
    #pragma unroll
    for (int i = 0; i < 4; i++)
        #pragma unroll
        for (int j = 0; j < 4; j++)
            #pragma unroll
            for (int k = 0; k < 4; k++) acc[i][j][k] = 0.0f;

    uint4 ahf[2][4], alf[2][4], bhf[2][2], blf[2][2];

    const uint4* Xh = g_Xfh; const uint4* Xl = g_Xfl;
    const uint4* Wh = g_Wqfh; const uint4* Wl = g_Wqfl;

    #pragma unroll
    for (int mf = 0; mf < 4; mf++) {
        size_t o = ((size_t)(mt0 + mf) * 16 + 0) * 32 + lane;
        ahf[0][mf] = Xh[o]; alf[0][mf] = Xl[o];
    }
    #pragma unroll
    for (int nf = 0; nf < 2; nf++) {
        size_t o = ((size_t)(nt0 + nf) * 16 + 0) * 32 + lane;
        bhf[0][nf] = Wh[o]; blf[0][nf] = Wl[o];
    }

    #pragma unroll
    for (int kcg = 0; kcg < 16; kcg++) {
        const int cur = kcg & 1;
        if (kcg < 15) {
            const int nxt = cur ^ 1;
            #pragma unroll
            for (int mf = 0; mf < 4; mf++) {
                size_t o = ((size_t)(mt0 + mf) * 16 + (kcg + 1)) * 32 + lane;
                ahf[nxt][mf] = Xh[o]; alf[nxt][mf] = Xl[o];
            }
            #pragma unroll
            for (int nf = 0; nf < 2; nf++) {
                size_t o = ((size_t)(nt0 + nf) * 16 + (kcg + 1)) * 32 + lane;
                bhf[nxt][nf] = Wh[o]; blf[nxt][nf] = Wl[o];
            }
        }
        #pragma unroll
        for (int mf = 0; mf < 4; mf++) {
            const uint32_t* a = reinterpret_cast<const uint32_t*>(&ahf[cur][mf]);
            #pragma unroll
            for (int nf = 0; nf < 2; nf++) {
                const uint32_t* b = reinterpret_cast<const uint32_t*>(&bhf[cur][nf]);
                mma16816(acc[mf][2*nf],   a, b + 0);
                mma16816(acc[mf][2*nf+1], a, b + 2);
            }
        }
        #pragma unroll
        for (int mf = 0; mf < 4; mf++) {
            const uint32_t* a = reinterpret_cast<const uint32_t*>(&ahf[cur][mf]);
            #pragma unroll
            for (int nf = 0; nf < 2; nf++) {
                const uint32_t* b = reinterpret_cast<const uint32_t*>(&blf[cur][nf]);
                mma16816(acc[mf][2*nf],   a, b + 0);
                mma16816(acc[mf][2*nf+1], a, b + 2);
            }
        }
        #pragma unroll
        for (int mf = 0; mf < 4; mf++) {
            const uint32_t* a = reinterpret_cast<const uint32_t*>(&alf[cur][mf]);
            #pragma unroll
            for (int nf = 0; nf < 2; nf++) {
                const uint32_t* b = reinterpret_cast<const uint32_t*>(&bhf[cur][nf]);
                mma16816(acc[mf][2*nf],   a, b + 0);
                mma16816(acc[mf][2*nf+1], a, b + 2);
            }
        }
    }

    const int which = n_blk >> 9;
    const int h = (n_blk >> 6) & 7;

    if (which == 0) {
        #pragma unroll
        for (int mf = 0; mf < 4; mf++) {
            int r0 = m_blk + mw + mf*16 + g;
            int bh = (r0 >> 10) * HEADS + h;
            int mt = (r0 & 1023) >> 4;
            #pragma unroll
            for (int kco = 0; kco < 2; kco++) {
                int j0 = 2*kco, j1 = j0 + 1;
                uint32_t h0,l0,h1,l1,h2,l2,h3,l3;
                split_pair(acc[mf][j0][0]*QK_SCALE, acc[mf][j0][1]*QK_SCALE, h0, l0);
                split_pair(acc[mf][j0][2]*QK_SCALE, acc[mf][j0][3]*QK_SCALE, h1, l1);
                split_pair(acc[mf][j1][0]*QK_SCALE, acc[mf][j1][1]*QK_SCALE, h2, l2);
                split_pair(acc[mf][j1][2]*QK_SCALE, acc[mf][j1][3]*QK_SCALE, h3, l3);
                int kcg = (nw >> 4) + kco;
                size_t o = ((size_t)(bh*64 + mt)*4 + kcg)*32 + lane;
                g_Qfh[o] = make_uint4(h0, h1, h2, h3);
                g_Qfl[o] = make_uint4(l0, l1, l2, l3);
            }
        }
    } else if (which == 1) {
        #pragma unroll
        for (int mf = 0; mf < 4; mf++) {
            int r0 = m_blk + mw + mf*16 + g;
            int bh = (r0 >> 10) * HEADS + h;
            int nt = (r0 & 1023) >> 4;
            #pragma unroll
            for (int kco = 0; kco < 2; kco++) {
                int j0 = 2*kco, j1 = j0 + 1;
                uint32_t h0,l0,h1,l1,h2,l2,h3,l3;
                split_pair(acc[mf][j0][0], acc[mf][j0][1], h0, l0);
                split_pair(acc[mf][j1][0], acc[mf][j1][1], h1, l1);
                split_pair(acc[mf][j0][2], acc[mf][j0][3], h2, l2);
                split_pair(acc[mf][j1][2], acc[mf][j1][3], h3, l3);
                int kcg = (nw >> 4) + kco;
                size_t o = ((size_t)(bh*64 + nt)*4 + kcg)*32 + lane;
                g_Kfh[o] = make_uint4(h0, h1, h2, h3);
                g_Kfl[o] = make_uint4(l0, l1, l2, l3);
            }
        }
    } else {
        const int tigl = lane & 3;
        int odd = g & 1;
        #pragma unroll
        for (int mf = 0; mf < 4; mf++) {
            int r0 = m_blk + mw + mf*16 + g;
            int bh = (r0 >> 10) * HEADS + h;
            int kcgv = (r0 & 1023) >> 4;
            #pragma unroll
            for (int kco = 0; kco < 2; kco++) {
                int j0 = 2*kco, j1 = j0 + 1;
                float o00 = __shfl_xor_sync(0xffffffffu, acc[mf][j0][0], 4);
                float o01 = __shfl_xor_sync(0xffffffffu, acc[mf][j0][1], 4);
                float o02 = __shfl_xor_sync(0xffffffffu, acc[mf][j0][2], 4);
                float o03 = __shfl_xor_sync(0xffffffffu, acc[mf][j0][3], 4);
                float o10 = __shfl_xor_sync(0xffffffffu, acc[mf][j1][0], 4);
                float o11 = __shfl_xor_sync(0xffffffffu, acc[mf][j1][1], 4);
                float o12 = __shfl_xor_sync(0xffffffffu, acc[mf][j1][2], 4);
                float o13 = __shfl_xor_sync(0xffffffffu, acc[mf][j1][3], 4);
                float aE = odd ? o01 : acc[mf][j0][0];
                float aO = odd ? acc[mf][j0][1] : o00;
                float bE = odd ? o03 : acc[mf][j0][2];
                float bO = odd ? acc[mf][j0][3] : o02;
                float cE = odd ? o11 : acc[mf][j1][0];
                float cO = odd ? acc[mf][j1][1] : o10;
                float dE = odd ? o13 : acc[mf][j1][2];
                float dO = odd ? acc[mf][j1][3] : o12;
                uint32_t h0,l0,h1,l1,h2,l2,h3,l3;
                split_pair(aE, aO, h0, l0);
                split_pair(bE, bO, h1, l1);
                split_pair(cE, cO, h2, l2);
                split_pair(dE, dO, h3, l3);
                int lane_t = tigl*8 + odd*4 + (g >> 1);
                int vt = (nw >> 4) + kco;
                size_t o = ((size_t)(bh*4 + vt)*64 + kcgv)*32 + lane_t;
                g_Vfh[o] = make_uint4(h0, h1, h2, h3);
                g_Vfl[o] = make_uint4(l0, l1, l2, l3);
            }
        }
    }
}

// ---------------------------------------------------------------------------
// Kernel 2: attention — frag-packed K/V staged through smem via cp.async
// (double-buffered, single barrier/stage). Reads are plain conflict-free
// ld.shared.v4; no ldmatrix, no swizzle.
// Stage (32 KB): Kh[0,8K) Kl[8,16K) Vh[16,24K) Vl[24,32K)
//   K region: [nt(4)][kcg(4)][lane(32)] uint4  (contiguous 8 KB in gmem)
//   V region: [vp(4)][jc(4)][lane(32)] uint4   (4 x 2 KB gmem chunks)
// ---------------------------------------------------------------------------
__global__ __launch_bounds__(128) void attn_mma_kernel()
{
    extern __shared__ uint8_t dyn_s[];
    const uint32_t sbase = smem_u32(dyn_s);

    const int tid  = threadIdx.x;
    const int lane = tid & 31;
    const int wid  = tid >> 5;
    const int bh   = blockIdx.y;
    const int qb   = blockIdx.x * 64 + wid * 16;
    const int g    = lane >> 2;
    const int tig  = lane & 3;

    // Q fragments (packed) — loaded once
    uint4 qh4[4], ql4[4];
    {
        int mt = qb >> 4;
        #pragma unroll
        for (int kcg = 0; kcg < 4; kcg++) {
            size_t o = ((size_t)(bh*64 + mt)*4 + kcg)*32 + lane;
            qh4[kcg] = g_Qfh[o];
            ql4[kcg] = g_Qfl[o];
        }
    }

    float oc[8][4];
    #pragma unroll
    for (int i = 0; i < 8; i++)
        #pragma unroll
        for (int j = 0; j < 4; j++) oc[i][j] = 0.0f;
    float lsum0 = 0.0f, lsum1 = 0.0f;

    auto preload = [&](int kt, int buf) {
        uint32_t b0 = sbase + buf * 32768;
        // K: contiguous 8 KB (512 uint4) per hi/lo
        const uint4* srcKh = g_Kfh + (size_t)(bh*64 + kt*4) * 128;
        const uint4* srcKl = g_Kfl + (size_t)(bh*64 + kt*4) * 128;
        #pragma unroll
        for (int i = 0; i < 4; i++) {
            int idx = i * 128 + tid;
            cp16(b0 + idx*16,        srcKh + idx);
            cp16(b0 + 8192 + idx*16, srcKl + idx);
        }
        // V: 4 chunks of 2 KB (128 uint4) per vp
        #pragma unroll
        for (int vp = 0; vp < 4; vp++) {
            const uint4* srcVh = g_Vfh + ((size_t)(bh*4 + vp)*64 + kt*4) * 32;
            const uint4* srcVl = g_Vfl + ((size_t)(bh*4 + vp)*64 + kt*4) * 32;
            cp16(b0 + 16384 + vp*2048 + tid*16, srcVh + tid);
            cp16(b0 + 24576 + vp*2048 + tid*16, srcVl + tid);
        }
        asm volatile("cp.async.commit_group;" ::: "memory");
    };

    preload(0, 0);

    for (int kt = 0; kt < 16; kt++) {
        asm volatile("cp.async.wait_group 0;" ::: "memory");
        __syncthreads();
        if (kt < 15) preload(kt + 1, (kt + 1) & 1);

        const uint32_t b0 = sbase + (kt & 1) * 32768;
        const uint32_t sKh = b0, sKl = b0 + 8192;
        const uint32_t sVh = b0 + 16384, sVl = b0 + 24576;

        // ---- S = Qh*Kh + Qh*Kl + Ql*Kh ----
        float s[8][4];
        #pragma unroll
        for (int i = 0; i < 8; i++)
            #pragma unroll
            for (int j = 0; j < 4; j++) s[i][j] = 0.0f;

        #pragma unroll
        for (int kcg = 0; kcg < 4; kcg++) {
            uint4 kh4[4], kl4[4];
            #pragma unroll
            for (int np = 0; np < 4; np++) {
                uint32_t off = (uint32_t)(((np*4 + kcg)*32 + lane) * 16);
                kh4[np] = lds128(sKh + off);
                kl4[np] = lds128(sKl + off);
            }
            const uint32_t* qh = reinterpret_cast<const uint32_t*>(&qh4[kcg]);
            const uint32_t* ql = reinterpret_cast<const uint32_t*>(&ql4[kcg]);
            #pragma unroll
            for (int np = 0; np < 4; np++) {
                const uint32_t* b = reinterpret_cast<const uint32_t*>(&kh4[np]);
                mma16816(s[2*np],   qh, b + 0);
                mma16816(s[2*np+1], qh, b + 2);
            }
            #pragma unroll
            for (int np = 0; np < 4; np++) {
                const uint32_t* b = reinterpret_cast<const uint32_t*>(&kl4[np]);
                mma16816(s[2*np],   qh, b + 0);
                mma16816(s[2*np+1], qh, b + 2);
            }
            #pragma unroll
            for (int np = 0; np < 4; np++) {
                const uint32_t* b = reinterpret_cast<const uint32_t*>(&kh4[np]);
                mma16816(s[2*np],   ql, b + 0);
                mma16816(s[2*np+1], ql, b + 2);
            }
        }

        // ---- exp + pack P ----
        uint32_t ph[4][4], pl[4][4];
        #pragma unroll
        for (int np = 0; np < 4; np++) {
            float p0[4], p1[4];
            #pragma unroll
            for (int j = 0; j < 4; j++) {
                p0[j] = __expf(s[2*np][j]);
                p1[j] = __expf(s[2*np+1][j]);
            }
            lsum0 += p0[0] + p0[1] + p1[0] + p1[1];
            lsum1 += p0[2] + p0[3] + p1[2] + p1[3];
            split_pair(p0[0], p0[1], ph[np][0], pl[np][0]);
            split_pair(p0[2], p0[3], ph[np][1], pl[np][1]);
            split_pair(p1[0], p1[1], ph[np][2], pl[np][2]);
            split_pair(p1[2], p1[3], ph[np][3], pl[np][3]);
        }

        // ---- O += Ph*Vh + Ph*Vl + Pl*Vh ----
        #pragma unroll
        for (int jc = 0; jc < 4; jc++) {
            uint4 vh4[4], vl4[4];
            #pragma unroll
            for (int vp = 0; vp < 4; vp++) {
                uint32_t off = (uint32_t)(((vp*4 + jc)*32 + lane) * 16);
                vh4[vp] = lds128(sVh + off);
                vl4[vp] = lds128(sVl + off);
            }
            #pragma unroll
            for (int vp = 0; vp < 4; vp++) {
                const uint32_t* b = reinterpret_cast<const uint32_t*>(&vh4[vp]);
                mma16816(oc[2*vp],   ph[jc], b + 0);
                mma16816(oc[2*vp+1], ph[jc], b + 2);
            }
            #pragma unroll
            for (int vp = 0; vp < 4; vp++) {
                const uint32_t* b = reinterpret_cast<const uint32_t*>(&vl4[vp]);
                mma16816(oc[2*vp],   ph[jc], b + 0);
                mma16816(oc[2*vp+1], ph[jc], b + 2);
            }
            #pragma unroll
            for (int vp = 0; vp < 4; vp++) {
                const uint32_t* b = reinterpret_cast<const uint32_t*>(&vh4[vp]);
                mma16816(oc[2*vp],   pl[jc], b + 0);
                mma16816(oc[2*vp+1], pl[jc], b + 2);
            }
        }
    }

    lsum0 += __shfl_xor_sync(0xffffffffu, lsum0, 1);
    lsum0 += __shfl_xor_sync(0xffffffffu, lsum0, 2);
    lsum1 += __shfl_xor_sync(0xffffffffu, lsum1, 1);
    lsum1 += __shfl_xor_sync(0xffffffffu, lsum1, 2);
    float inv0 = 1.0f / lsum0;
    float inv1 = 1.0f / lsum1;

    int b = bh >> 3, h = bh & 7;
    int q0 = qb + g, q1 = qb + g + 8;
    size_t row0 = ((size_t)(b * AD + h * 64 + (q0 >> 4))) * NPOS + ((q0 & 15) << 6);
    size_t row1 = ((size_t)(b * AD + h * 64 + (q1 >> 4))) * NPOS + ((q1 & 15) << 6);
    #pragma unroll
    for (int ct = 0; ct < 8; ct++) {
        int c = ct * 8 + tig * 2;
        uint32_t hi, lo;
        split_pair(oc[ct][0] * inv0, oc[ct][1] * inv0, hi, lo);
        *reinterpret_cast<uint32_t*>(&g_A2h[row0 + c]) = hi;
        *reinterpret_cast<uint32_t*>(&g_A2l[row0 + c]) = lo;
        split_pair(oc[ct][2] * inv1, oc[ct][3] * inv1, hi, lo);
        *reinterpret_cast<uint32_t*>(&g_A2h[row1 + c]) = hi;
        *reinterpret_cast<uint32_t*>(&g_A2l[row1 + c]) = lo;
    }
}

// ---------------------------------------------------------------------------
// Kernel 3: out GEMM + fused GN partials (unchanged)
// ---------------------------------------------------------------------------
__global__ __launch_bounds__(128, 4) void out_mma_kernel(const float* __restrict__ bout)
{
    extern __shared__ uint8_t dyn_o[];
    const uint32_t sbase = smem_u32(dyn_o);

    const int tid = threadIdx.x, lane = tid & 31, wid = tid >> 5;
    const int m_blk = blockIdx.x * 64;
    const int n_blk = blockIdx.y * 64;
    const int bb = blockIdx.z;
    const int mw = (wid >> 1) * 32;
    const int nw = (wid & 1) * 32;
    const int g = lane >> 2, tig = lane & 3;

    float acc[2][4][4];
    #pragma unroll
    for (int i = 0; i < 2; i++)
        #pragma unroll
        for (int j = 0; j < 4; j++)
            #pragma unroll
            for (int k = 0; k < 4; k++) acc[i][j][k] = 0.0f;

    const __nv_bfloat16* A2h = g_A2h + (size_t)bb * AD * NPOS;
    const __nv_bfloat16* A2l = g_A2l + (size_t)bb * AD * NPOS;

    auto preload = [&](int ks, int buf) {
        uint32_t b0 = sbase + buf * 16384;
        int k0 = ks * 32;
        #pragma unroll
        for (int i = 0; i < 2; i++) {
            int idx = i * 128 + tid;
            int row = idx >> 3, ch = idx & 7;
            uint32_t off = (uint32_t)(row * 128 + ((ch ^ (row & 7)) << 4));
            size_t go = (size_t)(k0 + row) * NPOS + m_blk + ch * 8;
            cp16(b0 + off,        A2h + go);
            cp16(b0 + 4096 + off, A2l + go);
        }
        #pragma unroll
        for (int i = 0; i < 2; i++) {
            int idx = i * 128 + tid;
            int lrow = idx >> 2, ch = idx & 3;
            uint32_t off = swp_off(lrow, ch);
            size_t go = (size_t)(n_blk + lrow) * AD + k0 + ch * 8;
            cp16(b0 + 8192 + off,  g_Woh + go);
            cp16(b0 + 12288 + off, g_Wol + go);
        }
        asm volatile("cp.async.commit_group;" ::: "memory");
    };

    preload(0, 0);

    for (int s = 0; s < 16; s++) {
        asm volatile("cp.async.wait_group 0;" ::: "memory");
        __syncthreads();
        if (s < 15) preload(s + 1, (s + 1) & 1);

        uint32_t b0 = sbase + (s & 1) * 16384;
        const uint32_t sAh = b0, sAl = b0 + 4096, sBh = b0 + 8192, sBl = b0 + 12288;

        #pragma unroll
        for (int kc = 0; kc < 2; kc++) {
            uint32_t bh0[4], bl0[4], bh1[4], bl1[4];
            ldsm4(bh0, bfragP_addr(sBh, nw,      kc, lane));
            ldsm4(bh1, bfragP_addr(sBh, nw + 16, kc, lane));
            ldsm4(bl0, bfragP_addr(sBl, nw,      kc, lane));
            ldsm4(bl1, bfragP_addr(sBl, nw + 16, kc, lane));
            #pragma unroll
            for (int mf = 0; mf < 2; mf++) {
                uint32_t ah[4], al[4];
                ldsm4t(ah, afragT128_addr(sAh, kc*16, mw + mf*16, lane));
                ldsm4t(al, afragT128_addr(sAl, kc*16, mw + mf*16, lane));
                mma16816(acc[mf][0], ah, bh0 + 0); mma16816(acc[mf][1], ah, bh0 + 2);
                mma16816(acc[mf][2], ah, bh1 + 0); mma16816(acc[mf][3], ah, bh1 + 2);
                mma16816(acc[mf][0], ah, bl0 + 0); mma16816(acc[mf][1], ah, bl0 + 2);
                mma16816(acc[mf][2], ah, bl1 + 0); mma16816(acc[mf][3], ah, bl1 + 2);
                mma16816(acc[mf][0], al, bh0 + 0); mma16816(acc[mf][1], al, bh0 + 2);
                mma16816(acc[mf][2], al, bh1 + 0); mma16816(acc[mf][3], al, bh1 + 2);
            }
        }
    }

    float psum = 0.0f, psq = 0.0f;
    #pragma unroll
    for (int mf = 0; mf < 2; mf++) {
        int r0 = m_blk + mw + mf*16 + g;
        #pragma unroll
        for (int j = 0; j < 4; j++) {
            int d = n_blk + nw + j * 8 + tig * 2;
            float2 bv = *reinterpret_cast<const float2*>(&bout[d]);
            float2 v0 = make_float2(acc[mf][j][0] + bv.x, acc[mf][j][1] + bv.y);
            float2 v1 = make_float2(acc[mf][j][2] + bv.x, acc[mf][j][3] + bv.y);
            *reinterpret_cast<float2*>(&g_Y[((size_t)bb*NPOS + r0)*COUT + d]) = v0;
            *reinterpret_cast<float2*>(&g_Y[((size_t)bb*NPOS + r0 + 8)*COUT + d]) = v1;
            psum += v0.x + v0.y + v1.x + v1.y;
            psq  += v0.x*v0.x + v0.y*v0.y + v1.x*v1.x + v1.y*v1.y;
        }
    }

    __syncthreads();
    float* rs  = reinterpret_cast<float*>(dyn_o);
    float* rss = rs + 128;
    rs[tid] = psum; rss[tid] = psq;
    __syncthreads();
    for (int st = 64; st > 0; st >>= 1) {
        if (tid < st) { rs[tid] += rs[tid + st]; rss[tid] += rss[tid + st]; }
        __syncthreads();
    }
    if (tid == 0) {
        int p = bb * 64 + blockIdx.x * 4 + blockIdx.y;
        g_part[2*p]   = rs[0];
        g_part[2*p+1] = rss[0];
    }
}

// ---------------------------------------------------------------------------
// GN final + normalize
// ---------------------------------------------------------------------------
__global__ void gn_final_kernel()
{
    int b = threadIdx.x;
    if (b < NB) {
        float s = 0.0f, ss = 0.0f;
        #pragma unroll
        for (int i = 0; i < 64; i++) {
            s  += g_part[2*(b*64 + i)];
            ss += g_part[2*(b*64 + i) + 1];
        }
        const float inv_n = 1.0f / (float)(NPOS * COUT);
        float mean = s * inv_n;
        float var  = ss * inv_n - mean * mean;
        g_stats[2*b]     = mean;
        g_stats[2*b + 1] = rsqrtf(var + GN_EPS);
    }
}

__global__ __launch_bounds__(256) void gn_norm_kernel(
    const float* __restrict__ gamma, const float* __restrict__ beta,
    float* __restrict__ out)
{
    int idx4 = blockIdx.x * 256 + threadIdx.x;
    int b  = idx4 >> 16;
    int d4 = idx4 & 63;

    float mean = g_stats[2*b];
    float rstd = g_stats[2*b + 1];

    float4 y  = reinterpret_cast<const float4*>(g_Y)[idx4];
    float4 g  = reinterpret_cast<const float4*>(gamma)[d4];
    float4 be = reinterpret_cast<const float4*>(beta)[d4];

    float4 r;
    r.x = (y.x - mean) * rstd * g.x + be.x;
    r.y = (y.y - mean) * rstd * g.y + be.y;
    r.z = (y.z - mean) * rstd * g.z + be.z;
    r.w = (y.w - mean) * rstd * g.w + be.w;
    reinterpret_cast<float4*>(out)[idx4] = r;
}

// ---------------------------------------------------------------------------
extern "C" void kernel_launch(void* const* d_in, const int* in_sizes, int n_in,
                              void* d_out, int out_size)
{
    const float* x      = (const float*)d_in[0];
    const float* w_qkv  = (const float*)d_in[1];
    const float* w_out  = (const float*)d_in[2];
    const float* b_out  = (const float*)d_in[3];
    const float* gamma  = (const float*)d_in[4];
    const float* beta   = (const float*)d_in[5];
    float* out = (float*)d_out;

    static int smem_set = 0;
    if (!smem_set) {
        cudaFuncSetAttribute(attn_mma_kernel,
                             cudaFuncAttributeMaxDynamicSharedMemorySize, 65536);
        cudaFuncSetAttribute(out_mma_kernel,
                             cudaFuncAttributeMaxDynamicSharedMemorySize, 32768);
        smem_set = 1;
    }

    conv_x_kernel<<<2048, 256>>>(x);
    conv_w_kernel<<<dim3(48, 8),  dim3(32, 32)>>>(w_qkv, CIN, 3*AD, 0);
    conv_w_kernel<<<dim3(8, 16),  dim3(32, 32)>>>(w_out, AD, COUT, 1);
    qkv_mma_kernel<<<dim3(24, 64), 128>>>();
    attn_mma_kernel<<<dim3(16, 64), 128, 65536>>>();
    out_mma_kernel<<<dim3(16, 4, 8), 128, 32768>>>(b_out);
    gn_final_kernel<<<1, 32>>>();
    gn_norm_kernel<<<2048, 256>>>(gamma, beta, out);
}

// round 12
// speedup vs baseline: 2.7779x; 2.1822x over previous
#include <cuda_runtime.h>
#include <cuda_fp16.h>
#include <cstdint>

#define NB    8
#define NPOS  1024
#define CIN   256
#define HEADS 8
#define DH    64
#define AD    512
#define COUT  256
#define QK_SCALE 0.125f
#define GN_EPS 1e-5f

// ---------------------------------------------------------------------------
// helpers
// ---------------------------------------------------------------------------
__device__ __forceinline__ uint32_t smem_u32(const void* p) {
    uint32_t a;
    asm("{ .reg .u64 t; cvta.to.shared.u64 t, %1; cvt.u32.u64 %0, t; }" : "=r"(a) : "l"(p));
    return a;
}

__device__ __forceinline__ uint32_t pack_h2(float a, float b)
{
    __half2 h = __floats2half2_rn(a, b);
    return *reinterpret_cast<uint32_t*>(&h);
}

// fp16 mma m16n8k16, fp32 accumulate
__device__ __forceinline__ void mma16816h(float* c, const uint32_t* a, const uint32_t* b)
{
    asm volatile("mma.sync.aligned.m16n8k16.row.col.f32.f16.f16.f32 "
        "{%0,%1,%2,%3},{%4,%5,%6,%7},{%8,%9},{%0,%1,%2,%3};"
        : "+f"(c[0]), "+f"(c[1]), "+f"(c[2]), "+f"(c[3])
        : "r"(a[0]), "r"(a[1]), "r"(a[2]), "r"(a[3]), "r"(b[0]), "r"(b[1]));
}

__device__ __forceinline__ void ldsm4(uint32_t* r, uint32_t addr)
{
    asm volatile("ldmatrix.sync.aligned.m8n8.x4.shared.b16 {%0,%1,%2,%3}, [%4];"
        : "=r"(r[0]), "=r"(r[1]), "=r"(r[2]), "=r"(r[3]) : "r"(addr));
}
__device__ __forceinline__ void ldsm4t(uint32_t* r, uint32_t addr)
{
    asm volatile("ldmatrix.sync.aligned.m8n8.x4.trans.shared.b16 {%0,%1,%2,%3}, [%4];"
        : "=r"(r[0]), "=r"(r[1]), "=r"(r[2]), "=r"(r[3]) : "r"(addr));
}

__device__ __forceinline__ void cp16(uint32_t dst, const void* src)
{
    asm volatile("cp.async.cg.shared.global [%0], [%1], 16;" :: "r"(dst), "l"(src));
}

__device__ __forceinline__ uint4 lds128(uint32_t addr)
{
    uint4 v;
    asm volatile("ld.shared.v4.u32 {%0,%1,%2,%3}, [%4];"
        : "=r"(v.x), "=r"(v.y), "=r"(v.z), "=r"(v.w) : "r"(addr));
    return v;
}

// ---- smem tile helpers (out_mma path) ----
__device__ __forceinline__ uint32_t sw_addr(uint32_t base, int row, int ch) {
    return base + row * 128 + ((ch ^ (row & 7)) << 4);
}
__device__ __forceinline__ uint32_t afragT128_addr(uint32_t base, int k0, int m0, int lane) {
    int row = k0 + (lane & 7) + ((lane >> 4) & 1) * 8;
    int ch  = (m0 >> 3) + ((lane >> 3) & 1);
    return sw_addr(base, row, ch);
}
__device__ __forceinline__ uint32_t swp_off(int lrow, int ch) {
    int prow = lrow >> 1;
    int cp = ((lrow & 1) << 2) | ch;
    return (uint32_t)(prow * 128 + ((cp ^ (prow & 7)) << 4));
}
__device__ __forceinline__ uint32_t bfragP_addr(uint32_t base, int n0, int kc, int lane) {
    int lrow = n0 + (lane & 7) + ((lane >> 4) & 1) * 8;
    int ch   = 2 * kc + ((lane >> 3) & 1);
    return base + swp_off(lrow, ch);
}

// ---------------------------------------------------------------------------
// Scratch globals — fragment-packed fp16 operands
//   A-frag (m,k): lane=(m&7)*4+((k&7)>>1), reg=((m&8)>>3)|((k&8)>>2)
//   B-frag (n,k): lane=(n&7)*4+((k&7)>>1), reg=((k&8)>>3)|((n&8)>>2)
// ---------------------------------------------------------------------------
__device__ uint4 g_Xf[512 * 16 * 32];           // X A-frags [mt][kcg][lane]
__device__ uint4 g_Wqf[96 * 16 * 32];           // w_qkv B-frags [nt][kcg][lane]
__device__ __half g_Wo[COUT * AD];              // w_out [d][ch]
__device__ uint4 g_Qf[64 * 64 * 4 * 32];        // Q A-frags [bh][mt][kcg][lane]
__device__ uint4 g_Kf[64 * 64 * 4 * 32];        // K B-frags [bh][nt][kcg][lane]
__device__ uint4 g_Vf[64 * 4 * 64 * 32];        // V B-frags [bh][vt][kcg_key][lane]
__device__ __half g_A2[NB * AD * NPOS];         // [b][ch][pos]
__device__ float g_Y[NB * NPOS * COUT];
__device__ float g_part[1024];
__device__ float g_stats[2 * NB];

// ---------------------------------------------------------------------------
// Kernel 0a: X -> fp16 A-frag packed
// ---------------------------------------------------------------------------
__global__ __launch_bounds__(256) void conv_x_kernel(const float* __restrict__ X)
{
    int idx4 = blockIdx.x * 256 + threadIdx.x;
    int m  = idx4 >> 6;
    int c4 = (idx4 & 63) * 4;
    float4 v = reinterpret_cast<const float4*>(X)[idx4];

    uint32_t* Xf = reinterpret_cast<uint32_t*>(g_Xf);
    int mt = m >> 4;
    #pragma unroll
    for (int p = 0; p < 2; p++) {
        int c = c4 + p * 2;
        uint32_t pk = pack_h2(p ? v.z : v.x, p ? v.w : v.y);
        int kcg = c >> 4;
        int lane = (m & 7) * 4 + ((c & 7) >> 1);
        int reg  = ((m & 8) >> 3) | ((c & 8) >> 2);
        Xf[((size_t)(mt * 16 + kcg) * 32 + lane) * 4 + reg] = pk;
    }
}

// ---------------------------------------------------------------------------
// Kernel 0b: weight transpose + fp16.
// which=0: w_qkv -> B-frag packed; which=1: w_out -> linear [d][ch]
// ---------------------------------------------------------------------------
__global__ void conv_w_kernel(const float* __restrict__ src, int K, int N, int which)
{
    __shared__ float tile[32][33];
    int n0 = blockIdx.x * 32;
    int k0 = blockIdx.y * 32;
    int tx = threadIdx.x, ty = threadIdx.y;
    tile[ty][tx] = src[(size_t)(k0 + ty) * N + n0 + tx];
    __syncthreads();
    if (tx < 16) {
        uint32_t pk = pack_h2(tile[2*tx][ty], tile[2*tx+1][ty]);
        int k = k0 + 2 * tx;
        int n = n0 + ty;
        if (which == 0) {
            uint32_t* Wf = reinterpret_cast<uint32_t*>(g_Wqf);
            int nt = n >> 4, kcg = k >> 4;
            int lane = (n & 7) * 4 + ((k & 7) >> 1);
            int reg  = ((k & 8) >> 3) | ((n & 8) >> 2);
            Wf[((size_t)(nt * 16 + kcg) * 32 + lane) * 4 + reg] = pk;
        } else {
            *reinterpret_cast<uint32_t*>(&g_Wo[(size_t)n * K + k]) = pk;
        }
    }
}

// ---------------------------------------------------------------------------
// Kernel 1: QKV GEMM — no smem, fp16 single product. Block 128m x 64n,
// warp 64x32. Grid (24 n, 64 m). Frag-packed epilogue.
// ---------------------------------------------------------------------------
__global__ __launch_bounds__(128) void qkv_mma_kernel()
{
    const int tid = threadIdx.x, lane = tid & 31, wid = tid >> 5;
    const int n_blk = blockIdx.x * 64;
    const int m_blk = blockIdx.y * 128;
    const int mw = (wid >> 1) * 64;
    const int nw = (wid & 1) * 32;
    const int g = lane >> 2;

    const int mt0 = (m_blk + mw) >> 4;
    const int nt0 = (n_blk + nw) >> 4;

    float acc[4][4][4];
    #pragma unroll
    for (int i = 0; i < 4; i++)
        #pragma unroll
        for (int j = 0; j < 4; j++)
            #pragma unroll
            for (int k = 0; k < 4; k++) acc[i][j][k] = 0.0f;

    uint4 af[2][4], bf[2][2];

    #pragma unroll
    for (int mf = 0; mf < 4; mf++)
        af[0][mf] = g_Xf[((size_t)(mt0 + mf) * 16 + 0) * 32 + lane];
    #pragma unroll
    for (int nf = 0; nf < 2; nf++)
        bf[0][nf] = g_Wqf[((size_t)(nt0 + nf) * 16 + 0) * 32 + lane];

    #pragma unroll
    for (int kcg = 0; kcg < 16; kcg++) {
        const int cur = kcg & 1;
        if (kcg < 15) {
            const int nxt = cur ^ 1;
            #pragma unroll
            for (int mf = 0; mf < 4; mf++)
                af[nxt][mf] = g_Xf[((size_t)(mt0 + mf) * 16 + (kcg + 1)) * 32 + lane];
            #pragma unroll
            for (int nf = 0; nf < 2; nf++)
                bf[nxt][nf] = g_Wqf[((size_t)(nt0 + nf) * 16 + (kcg + 1)) * 32 + lane];
        }
        #pragma unroll
        for (int mf = 0; mf < 4; mf++) {
            const uint32_t* a = reinterpret_cast<const uint32_t*>(&af[cur][mf]);
            #pragma unroll
            for (int nf = 0; nf < 2; nf++) {
                const uint32_t* b = reinterpret_cast<const uint32_t*>(&bf[cur][nf]);
                mma16816h(acc[mf][2*nf],   a, b + 0);
                mma16816h(acc[mf][2*nf+1], a, b + 2);
            }
        }
    }

    const int which = n_blk >> 9;
    const int h = (n_blk >> 6) & 7;

    if (which == 0) {
        #pragma unroll
        for (int mf = 0; mf < 4; mf++) {
            int r0 = m_blk + mw + mf*16 + g;
            int bh = (r0 >> 10) * HEADS + h;
            int mt = (r0 & 1023) >> 4;
            #pragma unroll
            for (int kco = 0; kco < 2; kco++) {
                int j0 = 2*kco, j1 = j0 + 1;
                uint32_t p0 = pack_h2(acc[mf][j0][0]*QK_SCALE, acc[mf][j0][1]*QK_SCALE);
                uint32_t p1 = pack_h2(acc[mf][j0][2]*QK_SCALE, acc[mf][j0][3]*QK_SCALE);
                uint32_t p2 = pack_h2(acc[mf][j1][0]*QK_SCALE, acc[mf][j1][1]*QK_SCALE);
                uint32_t p3 = pack_h2(acc[mf][j1][2]*QK_SCALE, acc[mf][j1][3]*QK_SCALE);
                int kcg = (nw >> 4) + kco;
                g_Qf[((size_t)(bh*64 + mt)*4 + kcg)*32 + lane] = make_uint4(p0, p1, p2, p3);
            }
        }
    } else if (which == 1) {
        #pragma unroll
        for (int mf = 0; mf < 4; mf++) {
            int r0 = m_blk + mw + mf*16 + g;
            int bh = (r0 >> 10) * HEADS + h;
            int nt = (r0 & 1023) >> 4;
            #pragma unroll
            for (int kco = 0; kco < 2; kco++) {
                int j0 = 2*kco, j1 = j0 + 1;
                uint32_t p0 = pack_h2(acc[mf][j0][0], acc[mf][j0][1]);
                uint32_t p1 = pack_h2(acc[mf][j1][0], acc[mf][j1][1]);
                uint32_t p2 = pack_h2(acc[mf][j0][2], acc[mf][j0][3]);
                uint32_t p3 = pack_h2(acc[mf][j1][2], acc[mf][j1][3]);
                int kcg = (nw >> 4) + kco;
                g_Kf[((size_t)(bh*64 + nt)*4 + kcg)*32 + lane] = make_uint4(p0, p1, p2, p3);
            }
        }
    } else {
        const int tigl = lane & 3;
        int odd = g & 1;
        #pragma unroll
        for (int mf = 0; mf < 4; mf++) {
            int r0 = m_blk + mw + mf*16 + g;
            int bh = (r0 >> 10) * HEADS + h;
            int kcgv = (r0 & 1023) >> 4;
            #pragma unroll
            for (int kco = 0; kco < 2; kco++) {
                int j0 = 2*kco, j1 = j0 + 1;
                float o00 = __shfl_xor_sync(0xffffffffu, acc[mf][j0][0], 4);
                float o01 = __shfl_xor_sync(0xffffffffu, acc[mf][j0][1], 4);
                float o02 = __shfl_xor_sync(0xffffffffu, acc[mf][j0][2], 4);
                float o03 = __shfl_xor_sync(0xffffffffu, acc[mf][j0][3], 4);
                float o10 = __shfl_xor_sync(0xffffffffu, acc[mf][j1][0], 4);
                float o11 = __shfl_xor_sync(0xffffffffu, acc[mf][j1][1], 4);
                float o12 = __shfl_xor_sync(0xffffffffu, acc[mf][j1][2], 4);
                float o13 = __shfl_xor_sync(0xffffffffu, acc[mf][j1][3], 4);
                float aE = odd ? o01 : acc[mf][j0][0];
                float aO = odd ? acc[mf][j0][1] : o00;
                float bE = odd ? o03 : acc[mf][j0][2];
                float bO = odd ? acc[mf][j0][3] : o02;
                float cE = odd ? o11 : acc[mf][j1][0];
                float cO = odd ? acc[mf][j1][1] : o10;
                float dE = odd ? o13 : acc[mf][j1][2];
                float dO = odd ? acc[mf][j1][3] : o12;
                uint32_t p0 = pack_h2(aE, aO);
                uint32_t p1 = pack_h2(bE, bO);
                uint32_t p2 = pack_h2(cE, cO);
                uint32_t p3 = pack_h2(dE, dO);
                int lane_t = tigl*8 + odd*4 + (g >> 1);
                int vt = (nw >> 4) + kco;
                g_Vf[((size_t)(bh*4 + vt)*64 + kcgv)*32 + lane_t] = make_uint4(p0, p1, p2, p3);
            }
        }
    }
}

// ---------------------------------------------------------------------------
// Kernel 2: attention — fp16 single product. Frag-packed K/V staged through
// smem via cp.async (double-buffered, single barrier/stage); plain lds128.
// Stage (16 KB): Kf[0,8K) Vf[8,16K)
// ---------------------------------------------------------------------------
__global__ __launch_bounds__(128) void attn_mma_kernel()
{
    extern __shared__ uint8_t dyn_s[];
    const uint32_t sbase = smem_u32(dyn_s);

    const int tid  = threadIdx.x;
    const int lane = tid & 31;
    const int wid  = tid >> 5;
    const int bh   = blockIdx.y;
    const int qb   = blockIdx.x * 64 + wid * 16;
    const int g    = lane >> 2;
    const int tig  = lane & 3;

    // Q fragments
    uint4 qf[4];
    {
        int mt = qb >> 4;
        #pragma unroll
        for (int kcg = 0; kcg < 4; kcg++)
            qf[kcg] = g_Qf[((size_t)(bh*64 + mt)*4 + kcg)*32 + lane];
    }

    float oc[8][4];
    #pragma unroll
    for (int i = 0; i < 8; i++)
        #pragma unroll
        for (int j = 0; j < 4; j++) oc[i][j] = 0.0f;
    float lsum0 = 0.0f, lsum1 = 0.0f;

    auto preload = [&](int kt, int buf) {
        uint32_t b0 = sbase + buf * 16384;
        const uint4* srcK = g_Kf + (size_t)(bh*64 + kt*4) * 128;   // 512 uint4
        #pragma unroll
        for (int i = 0; i < 4; i++) {
            int idx = i * 128 + tid;
            cp16(b0 + idx*16, srcK + idx);
        }
        #pragma unroll
        for (int vp = 0; vp < 4; vp++) {
            const uint4* srcV = g_Vf + ((size_t)(bh*4 + vp)*64 + kt*4) * 32; // 128 uint4
            cp16(b0 + 8192 + vp*2048 + tid*16, srcV + tid);
        }
        asm volatile("cp.async.commit_group;" ::: "memory");
    };

    preload(0, 0);

    for (int kt = 0; kt < 16; kt++) {
        asm volatile("cp.async.wait_group 0;" ::: "memory");
        __syncthreads();
        if (kt < 15) preload(kt + 1, (kt + 1) & 1);

        const uint32_t b0 = sbase + (kt & 1) * 16384;
        const uint32_t sK = b0, sV = b0 + 8192;

        // ---- S = Q*K ----
        float s[8][4];
        #pragma unroll
        for (int i = 0; i < 8; i++)
            #pragma unroll
            for (int j = 0; j < 4; j++) s[i][j] = 0.0f;

        #pragma unroll
        for (int kcg = 0; kcg < 4; kcg++) {
            const uint32_t* q = reinterpret_cast<const uint32_t*>(&qf[kcg]);
            #pragma unroll
            for (int np = 0; np < 4; np++) {
                uint4 k4 = lds128(sK + (uint32_t)(((np*4 + kcg)*32 + lane) * 16));
                const uint32_t* b = reinterpret_cast<const uint32_t*>(&k4);
                mma16816h(s[2*np],   q, b + 0);
                mma16816h(s[2*np+1], q, b + 2);
            }
        }

        // ---- exp + pack P (fp16) ----
        uint32_t pp[4][4];
        #pragma unroll
        for (int np = 0; np < 4; np++) {
            float p0[4], p1[4];
            #pragma unroll
            for (int j = 0; j < 4; j++) {
                p0[j] = __expf(s[2*np][j]);
                p1[j] = __expf(s[2*np+1][j]);
            }
            lsum0 += p0[0] + p0[1] + p1[0] + p1[1];
            lsum1 += p0[2] + p0[3] + p1[2] + p1[3];
            pp[np][0] = pack_h2(p0[0], p0[1]);
            pp[np][1] = pack_h2(p0[2], p0[3]);
            pp[np][2] = pack_h2(p1[0], p1[1]);
            pp[np][3] = pack_h2(p1[2], p1[3]);
        }

        // ---- O += P*V ----
        #pragma unroll
        for (int jc = 0; jc < 4; jc++) {
            #pragma unroll
            for (int vp = 0; vp < 4; vp++) {
                uint4 v4 = lds128(sV + (uint32_t)(((vp*4 + jc)*32 + lane) * 16));
                const uint32_t* b = reinterpret_cast<const uint32_t*>(&v4);
                mma16816h(oc[2*vp],   pp[jc], b + 0);
                mma16816h(oc[2*vp+1], pp[jc], b + 2);
            }
        }
    }

    lsum0 += __shfl_xor_sync(0xffffffffu, lsum0, 1);
    lsum0 += __shfl_xor_sync(0xffffffffu, lsum0, 2);
    lsum1 += __shfl_xor_sync(0xffffffffu, lsum1, 1);
    lsum1 += __shfl_xor_sync(0xffffffffu, lsum1, 2);
    float inv0 = 1.0f / lsum0;
    float inv1 = 1.0f / lsum1;

    int b = bh >> 3, h = bh & 7;
    int q0 = qb + g, q1 = qb + g + 8;
    size_t row0 = ((size_t)(b * AD + h * 64 + (q0 >> 4))) * NPOS + ((q0 & 15) << 6);
    size_t row1 = ((size_t)(b * AD + h * 64 + (q1 >> 4))) * NPOS + ((q1 & 15) << 6);
    #pragma unroll
    for (int ct = 0; ct < 8; ct++) {
        int c = ct * 8 + tig * 2;
        *reinterpret_cast<uint32_t*>(&g_A2[row0 + c]) =
            pack_h2(oc[ct][0] * inv0, oc[ct][1] * inv0);
        *reinterpret_cast<uint32_t*>(&g_A2[row1 + c]) =
            pack_h2(oc[ct][2] * inv1, oc[ct][3] * inv1);
    }
}

// ---------------------------------------------------------------------------
// Kernel 3: out GEMM + fused GN partials. fp16 single product.
// Block 64pos x 64d, warp 32x32, BK=32. Stage (8 KB): A[0,4K) B[4,8K).
// Grid (16, 4, 8).
// ---------------------------------------------------------------------------
__global__ __launch_bounds__(128) void out_mma_kernel(const float* __restrict__ bout)
{
    extern __shared__ uint8_t dyn_o[];
    const uint32_t sbase = smem_u32(dyn_o);

    const int tid = threadIdx.x, lane = tid & 31, wid = tid >> 5;
    const int m_blk = blockIdx.x * 64;
    const int n_blk = blockIdx.y * 64;
    const int bb = blockIdx.z;
    const int mw = (wid >> 1) * 32;
    const int nw = (wid & 1) * 32;
    const int g = lane >> 2, tig = lane & 3;

    float acc[2][4][4];
    #pragma unroll
    for (int i = 0; i < 2; i++)
        #pragma unroll
        for (int j = 0; j < 4; j++)
            #pragma unroll
            for (int k = 0; k < 4; k++) acc[i][j][k] = 0.0f;

    const __half* A2 = g_A2 + (size_t)bb * AD * NPOS;

    auto preload = [&](int ks, int buf) {
        uint32_t b0 = sbase + buf * 8192;
        int k0 = ks * 32;
        // A: 32 ch-rows x 64 pos fp16 (128B rows, swizzled)
        #pragma unroll
        for (int i = 0; i < 2; i++) {
            int idx = i * 128 + tid;
            int row = idx >> 3, ch = idx & 7;
            uint32_t off = (uint32_t)(row * 128 + ((ch ^ (row & 7)) << 4));
            cp16(b0 + off, A2 + (size_t)(k0 + row) * NPOS + m_blk + ch * 8);
        }
        // B: 64 d-rows x 32 ch fp16 (packed 64B rows)
        #pragma unroll
        for (int i = 0; i < 2; i++) {
            int idx = i * 128 + tid;
            int lrow = idx >> 2, ch = idx & 3;
            cp16(b0 + 4096 + swp_off(lrow, ch),
                 g_Wo + (size_t)(n_blk + lrow) * AD + k0 + ch * 8);
        }
        asm volatile("cp.async.commit_group;" ::: "memory");
    };

    preload(0, 0);

    for (int s = 0; s < 16; s++) {
        asm volatile("cp.async.wait_group 0;" ::: "memory");
        __syncthreads();
        if (s < 15) preload(s + 1, (s + 1) & 1);

        uint32_t b0 = sbase + (s & 1) * 8192;
        const uint32_t sA = b0, sB = b0 + 4096;

        #pragma unroll
        for (int kc = 0; kc < 2; kc++) {
            uint32_t b0f[4], b1f[4];
            ldsm4(b0f, bfragP_addr(sB, nw,      kc, lane));
            ldsm4(b1f, bfragP_addr(sB, nw + 16, kc, lane));
            #pragma unroll
            for (int mf = 0; mf < 2; mf++) {
                uint32_t a4[4];
                ldsm4t(a4, afragT128_addr(sA, kc*16, mw + mf*16, lane));
                mma16816h(acc[mf][0], a4, b0f + 0); mma16816h(acc[mf][1], a4, b0f + 2);
                mma16816h(acc[mf][2], a4, b1f + 0); mma16816h(acc[mf][3], a4, b1f + 2);
            }
        }
    }

    float psum = 0.0f, psq = 0.0f;
    #pragma unroll
    for (int mf = 0; mf < 2; mf++) {
        int r0 = m_blk + mw + mf*16 + g;
        #pragma unroll
        for (int j = 0; j < 4; j++) {
            int d = n_blk + nw + j * 8 + tig * 2;
            float2 bv = *reinterpret_cast<const float2*>(&bout[d]);
            float2 v0 = make_float2(acc[mf][j][0] + bv.x, acc[mf][j][1] + bv.y);
            float2 v1 = make_float2(acc[mf][j][2] + bv.x, acc[mf][j][3] + bv.y);
            *reinterpret_cast<float2*>(&g_Y[((size_t)bb*NPOS + r0)*COUT + d]) = v0;
            *reinterpret_cast<float2*>(&g_Y[((size_t)bb*NPOS + r0 + 8)*COUT + d]) = v1;
            psum += v0.x + v0.y + v1.x + v1.y;
            psq  += v0.x*v0.x + v0.y*v0.y + v1.x*v1.x + v1.y*v1.y;
        }
    }

    __syncthreads();
    float* rs  = reinterpret_cast<float*>(dyn_o);
    float* rss = rs + 128;
    rs[tid] = psum; rss[tid] = psq;
    __syncthreads();
    for (int st = 64; st > 0; st >>= 1) {
        if (tid < st) { rs[tid] += rs[tid + st]; rss[tid] += rss[tid + st]; }
        __syncthreads();
    }
    if (tid == 0) {
        int p = bb * 64 + blockIdx.x * 4 + blockIdx.y;
        g_part[2*p]   = rs[0];
        g_part[2*p+1] = rss[0];
    }
}

// ---------------------------------------------------------------------------
// GN final + normalize
// ---------------------------------------------------------------------------
__global__ void gn_final_kernel()
{
    int b = threadIdx.x;
    if (b < NB) {
        float s = 0.0f, ss = 0.0f;
        #pragma unroll
        for (int i = 0; i < 64; i++) {
            s  += g_part[2*(b*64 + i)];
            ss += g_part[2*(b*64 + i) + 1];
        }
        const float inv_n = 1.0f / (float)(NPOS * COUT);
        float mean = s * inv_n;
        float var  = ss * inv_n - mean * mean;
        g_stats[2*b]     = mean;
        g_stats[2*b + 1] = rsqrtf(var + GN_EPS);
    }
}

__global__ __launch_bounds__(256) void gn_norm_kernel(
    const float* __restrict__ gamma, const float* __restrict__ beta,
    float* __restrict__ out)
{
    int idx4 = blockIdx.x * 256 + threadIdx.x;
    int b  = idx4 >> 16;
    int d4 = idx4 & 63;

    float mean = g_stats[2*b];
    float rstd = g_stats[2*b + 1];

    float4 y  = reinterpret_cast<const float4*>(g_Y)[idx4];
    float4 g  = reinterpret_cast<const float4*>(gamma)[d4];
    float4 be = reinterpret_cast<const float4*>(beta)[d4];

    float4 r;
    r.x = (y.x - mean) * rstd * g.x + be.x;
    r.y = (y.y - mean) * rstd * g.y + be.y;
    r.z = (y.z - mean) * rstd * g.z + be.z;
    r.w = (y.w - mean) * rstd * g.w + be.w;
    reinterpret_cast<float4*>(out)[idx4] = r;
}

// ---------------------------------------------------------------------------
extern "C" void kernel_launch(void* const* d_in, const int* in_sizes, int n_in,
                              void* d_out, int out_size)
{
    const float* x      = (const float*)d_in[0];
    const float* w_qkv  = (const float*)d_in[1];
    const float* w_out  = (const float*)d_in[2];
    const float* b_out  = (const float*)d_in[3];
    const float* gamma  = (const float*)d_in[4];
    const float* beta   = (const float*)d_in[5];
    float* out = (float*)d_out;

    static int smem_set = 0;
    if (!smem_set) {
        cudaFuncSetAttribute(attn_mma_kernel,
                             cudaFuncAttributeMaxDynamicSharedMemorySize, 32768);
        cudaFuncSetAttribute(out_mma_kernel,
                             cudaFuncAttributeMaxDynamicSharedMemorySize, 16384);
        smem_set = 1;
    }

    conv_x_kernel<<<2048, 256>>>(x);
    conv_w_kernel<<<dim3(48, 8),  dim3(32, 32)>>>(w_qkv, CIN, 3*AD, 0);
    conv_w_kernel<<<dim3(8, 16),  dim3(32, 32)>>>(w_out, AD, COUT, 1);
    qkv_mma_kernel<<<dim3(24, 64), 128>>>();
    attn_mma_kernel<<<dim3(16, 64), 128, 32768>>>();
    out_mma_kernel<<<dim3(16, 4, 8), 128, 16384>>>(b_out);
    gn_final_kernel<<<1, 32>>>();
    gn_norm_kernel<<<2048, 256>>>(gamma, beta, out);
}